// round 14
// baseline (speedup 1.0000x reference)
#include <cuda_runtime.h>
#include <cuda_fp16.h>
#include <cuda_bf16.h>

#define BATCH   512
#define CIN     2048
#define OFEAT   64
#define KDIM    16
#define MCOLS   1024
#define OUTW    2112

// Scratch (device globals; no allocs)
__device__ __nv_bfloat16 g_xh[BATCH * CIN];     // 2 MB
__device__ __nv_bfloat16 g_Th[CIN * MCOLS];     // 4 MB, [k][n]
__device__ __half        g_mh[BATCH * MCOLS];   // 1 MB

// ---------------------------------------------------------------------------
// Prep: convert x,T -> bf16, zero out[:, 2048:]. Uniform regions by blockIdx,
// 2 float4 per thread. blocks [0,512): x; [512,1536): T; [1536,1552): zero.
// ---------------------------------------------------------------------------
__global__ __launch_bounds__(256) void prep_kernel(
    const float* __restrict__ x, const float* __restrict__ T, float* __restrict__ out)
{
    const int bid = blockIdx.x;
    const int tid = threadIdx.x;
    if (bid < 512) {
        int base = bid * 512 + tid;
#pragma unroll
        for (int it = 0; it < 2; ++it) {
            int id = base + it * 256;
            float4 v = ((const float4*)x)[id];
            __nv_bfloat162* dst = (__nv_bfloat162*)&g_xh[id * 4];
            dst[0] = __floats2bfloat162_rn(v.x, v.y);
            dst[1] = __floats2bfloat162_rn(v.z, v.w);
        }
    } else if (bid < 1536) {
        int base = (bid - 512) * 512 + tid;
#pragma unroll
        for (int it = 0; it < 2; ++it) {
            int i = base + it * 256;
            float4 v = ((const float4*)T)[i];
            __nv_bfloat162* dst = (__nv_bfloat162*)&g_Th[i * 4];
            dst[0] = __floats2bfloat162_rn(v.x, v.y);
            dst[1] = __floats2bfloat162_rn(v.z, v.w);
        }
    } else {
        int base = (bid - 1536) * 512 + tid;
#pragma unroll
        for (int it = 0; it < 2; ++it) {
            int i = base + it * 256;
            int row = i >> 4, c = i & 15;
            ((float4*)&out[row * OUTW + CIN])[c] = make_float4(0.f, 0.f, 0.f, 0.f);
        }
    }
}

// ---------------------------------------------------------------------------
// GEMM bf16 (R9 config): m = x @ T, mma.m16n8k16, 4-stage cp.async ring.
// BM=32 BN=64 BK=32, 128 threads (4 warps, 2m x 2n, warp tile 16x32).
// ---------------------------------------------------------------------------
__device__ __forceinline__ void cp16(unsigned s, const void* g) {
    asm volatile("cp.async.cg.shared.global [%0], [%1], 16;" :: "r"(s), "l"(g));
}
#define CP_COMMIT()  asm volatile("cp.async.commit_group;")
#define CP_WAIT(N)   asm volatile("cp.async.wait_group %0;" :: "n"(N))

__device__ __forceinline__ void ldm_x4(unsigned* r, unsigned addr) {
    asm volatile("ldmatrix.sync.aligned.m8n8.x4.shared.b16 {%0,%1,%2,%3}, [%4];"
        : "=r"(r[0]), "=r"(r[1]), "=r"(r[2]), "=r"(r[3]) : "r"(addr));
}
__device__ __forceinline__ void ldm_x4t(unsigned* r, unsigned addr) {
    asm volatile("ldmatrix.sync.aligned.m8n8.x4.trans.shared.b16 {%0,%1,%2,%3}, [%4];"
        : "=r"(r[0]), "=r"(r[1]), "=r"(r[2]), "=r"(r[3]) : "r"(addr));
}
__device__ __forceinline__ void mma_bf16(float* d, const unsigned* a, const unsigned* b) {
    asm volatile(
        "mma.sync.aligned.m16n8k16.row.col.f32.bf16.bf16.f32 "
        "{%0,%1,%2,%3}, {%4,%5,%6,%7}, {%8,%9}, {%0,%1,%2,%3};\n"
        : "+f"(d[0]), "+f"(d[1]), "+f"(d[2]), "+f"(d[3])
        : "r"(a[0]), "r"(a[1]), "r"(a[2]), "r"(a[3]), "r"(b[0]), "r"(b[1]));
}

#define NSTAGE 4
#define NPANEL 64

__global__ __launch_bounds__(128) void gemm_bf16(__half* __restrict__ mh)
{
    __shared__ __nv_bfloat16 As[NSTAGE][32][40];
    __shared__ __nv_bfloat16 Bs[NSTAGE][32][72];

    const int tid  = threadIdx.x;
    const int lane = tid & 31;
    const int wid  = tid >> 5;
    const int wm   = wid & 1;
    const int wn   = wid >> 1;
    const int row0 = blockIdx.y * 32;
    const int col0 = blockIdx.x * 64;

    const int aRow = tid >> 2, aC = (tid & 3) * 8;
    const int bRow = tid >> 2, bC = (tid & 3) * 16;

    const __nv_bfloat16* gA = &g_xh[(row0 + aRow) * CIN + aC];
    const __nv_bfloat16* gB = &g_Th[bRow * MCOLS + col0 + bC];

    float d[2][2][4];
#pragma unroll
    for (int i = 0; i < 2; ++i)
#pragma unroll
        for (int j = 0; j < 2; ++j)
#pragma unroll
            for (int k = 0; k < 4; ++k) d[i][j][k] = 0.0f;

#pragma unroll
    for (int s = 0; s < NSTAGE - 1; ++s) {
        cp16(__cvta_generic_to_shared(&As[s][aRow][aC]), gA + s * 32);
        cp16(__cvta_generic_to_shared(&Bs[s][bRow][bC]),     gB + s * 32 * MCOLS);
        cp16(__cvta_generic_to_shared(&Bs[s][bRow][bC + 8]), gB + s * 32 * MCOLS + 8);
        CP_COMMIT();
    }

    for (int p = 0; p < NPANEL; ++p) {
        CP_WAIT(NSTAGE - 2);
        __syncthreads();
        if (p + NSTAGE - 1 < NPANEL) {
            const int s  = (p + NSTAGE - 1) & (NSTAGE - 1);
            const int k0 = (p + NSTAGE - 1) * 32;
            cp16(__cvta_generic_to_shared(&As[s][aRow][aC]), gA + k0);
            cp16(__cvta_generic_to_shared(&Bs[s][bRow][bC]),     gB + k0 * MCOLS);
            cp16(__cvta_generic_to_shared(&Bs[s][bRow][bC + 8]), gB + k0 * MCOLS + 8);
        }
        CP_COMMIT();
        const int buf = p & (NSTAGE - 1);

#pragma unroll
        for (int kk = 0; kk < 32; kk += 16) {
            unsigned a[4];
            unsigned adrA = __cvta_generic_to_shared(
                &As[buf][wm * 16 + (lane & 15)][kk + (lane >> 4) * 8]);
            ldm_x4(a, adrA);
#pragma unroll
            for (int bi = 0; bi < 2; ++bi) {
                unsigned bb[4];
                unsigned adrB = __cvta_generic_to_shared(
                    &Bs[buf][kk + (lane & 15)][wn * 32 + bi * 16 + (lane >> 4) * 8]);
                ldm_x4t(bb, adrB);
                mma_bf16(d[bi][0], a, bb);
                mma_bf16(d[bi][1], a, bb + 2);
            }
        }
    }

    const int g = lane >> 2, c = lane & 3;
#pragma unroll
    for (int bi = 0; bi < 2; ++bi)
#pragma unroll
        for (int h = 0; h < 2; ++h) {
            int row = row0 + wm * 16 + g;
            int col = col0 + wn * 32 + bi * 16 + h * 8 + c * 2;
            *(__half2*)&mh[row * MCOLS + col] =
                __floats2half2_rn(d[bi][h][0], d[bi][h][1]);
            *(__half2*)&mh[(row + 8) * MCOLS + col] =
                __floats2half2_rn(d[bi][h][2], d[bi][h][3]);
        }
}

// ---------------------------------------------------------------------------
// Pairwise v2: grid (jh=4, bt=4, o=64) = 1024 blocks x 128 thr; each block
// covers 128 j rows. 8-wide screen on full-row sums S (|dS| <= L1 dist);
// full path only on warp-vote pass (diagonal). Folds x->out (2 float4/thr).
// ---------------------------------------------------------------------------
__global__ __launch_bounds__(128) void pairwise_kernel(
    const __half* __restrict__ mh, const float* __restrict__ x, float* __restrict__ out)
{
    __shared__ uint4 sjt[128][2];                 // staged j rows
    __shared__ __align__(16) __half sgS[128];     // staged row sums

    const int jh  = blockIdx.x;
    const int bt  = blockIdx.y;
    const int o   = blockIdx.z;
    const int tid = threadIdx.x;
    const int b   = bt * 128 + tid;

    // folded x -> out copy: 2 float4 per thread
    {
        int lin = (o * 4 + bt) * 4 + jh;          // 0..1023
#pragma unroll
        for (int it = 0; it < 2; ++it) {
            int id  = lin * 256 + it * 128 + tid;
            int row = id >> 9, c4 = id & 511;
            ((float4*)&out[row * OUTW])[c4] = ((const float4*)&x[row * CIN])[c4];
        }
    }

    // own row + signature
    __half2 v[8];
    {
        const uint4* vp = (const uint4*)&mh[b * MCOLS + o * KDIM];
        *(uint4*)&v[0] = vp[0];
        *(uint4*)&v[4] = vp[1];
    }
    __half2 vS2;
    {
        __half2 t0 = __hadd2(__hadd2(v[0], v[1]), __hadd2(v[2], v[3]));
        __half2 t1 = __hadd2(__hadd2(v[4], v[5]), __hadd2(v[6], v[7]));
        __half2 t  = __hadd2(t0, t1);
        vS2 = __half2half2(__hadd(__low2half(t), __high2half(t)));
    }

    // stage j rows + sums (one row per thread)
    {
        int j = jh * 128 + tid;
        const uint4* jp = (const uint4*)&mh[j * MCOLS + o * KDIM];
        uint4 w0 = jp[0], w1 = jp[1];
        sjt[tid][0] = w0;
        sjt[tid][1] = w1;
        __half2 s[8];
        *(uint4*)&s[0] = w0;
        *(uint4*)&s[4] = w1;
        __half2 t0 = __hadd2(__hadd2(s[0], s[1]), __hadd2(s[2], s[3]));
        __half2 t1 = __hadd2(__hadd2(s[4], s[5]), __hadd2(s[6], s[7]));
        __half2 t  = __hadd2(t0, t1);
        sgS[tid] = __hadd(__low2half(t), __high2half(t));
    }
    __syncthreads();

    float acc = 0.0f;
#pragma unroll 4
    for (int gr = 0; gr < 16; ++gr) {             // 8 j's per group
        uint4 sv = *(const uint4*)&sgS[gr * 8];
        __half2 p0 = *(__half2*)&sv.x, p1 = *(__half2*)&sv.y;
        __half2 p2 = *(__half2*)&sv.z, p3 = *(__half2*)&sv.w;
        __half2 e0 = __habs2(__hsub2(vS2, p0));
        __half2 e1 = __habs2(__hsub2(vS2, p1));
        __half2 e2 = __habs2(__hsub2(vS2, p2));
        __half2 e3 = __habs2(__hsub2(vS2, p3));
        __half2 mm = __hmin2(__hmin2(e0, e1), __hmin2(e2, e3));
        float mn = __half2float(__hmin(__low2half(mm), __high2half(mm)));
        if (__any_sync(0xffffffffu, mn < 30.0f)) {
#pragma unroll
            for (int t = 0; t < 8; ++t) {
                const int jj = gr * 8 + t;
                __half2 s[8];
                *(uint4*)&s[0] = sjt[jj][0];
                *(uint4*)&s[4] = sjt[jj][1];
                __half2 q0 = __habs2(__hsub2(v[0], s[0]));
                __half2 q1 = __habs2(__hsub2(v[1], s[1]));
                __half2 q2 = __habs2(__hsub2(v[2], s[2]));
                __half2 q3 = __habs2(__hsub2(v[3], s[3]));
                __half2 q4 = __habs2(__hsub2(v[4], s[4]));
                __half2 q5 = __habs2(__hsub2(v[5], s[5]));
                __half2 q6 = __habs2(__hsub2(v[6], s[6]));
                __half2 q7 = __habs2(__hsub2(v[7], s[7]));
                __half2 sm = __hadd2(__hadd2(__hadd2(q0, q1), __hadd2(q2, q3)),
                                     __hadd2(__hadd2(q4, q5), __hadd2(q6, q7)));
                float dist = __low2float(sm) + __high2float(sm);
                acc += __expf(-dist);
            }
        }
    }

    atomicAdd(&out[b * OUTW + CIN + o], acc);
}

extern "C" void kernel_launch(void* const* d_in, const int* in_sizes, int n_in,
                              void* d_out, int out_size)
{
    const float* x = (const float*)d_in[0];
    const float* T = (const float*)d_in[1];
    float* out = (float*)d_out;

    __half* mh;
    cudaGetSymbolAddress((void**)&mh, g_mh);

    prep_kernel<<<1552, 256>>>(x, T, out);
    gemm_bf16<<<dim3(MCOLS / 64, BATCH / 32), 128>>>(mh);
    pairwise_kernel<<<dim3(4, 4, OFEAT), 128>>>(mh, x, out);
}

// round 15
// speedup vs baseline: 1.3746x; 1.3746x over previous
#include <cuda_runtime.h>
#include <cuda_fp16.h>
#include <cuda_bf16.h>

#define BATCH   512
#define CIN     2048
#define OFEAT   64
#define KDIM    16
#define MCOLS   1024
#define OUTW    2112

// Scratch (device globals; no allocs)
__device__ __nv_bfloat16 g_xh[BATCH * CIN];     // 2 MB
__device__ __nv_bfloat16 g_Th[CIN * MCOLS];     // 4 MB, [k][n]
__device__ __half        g_mh[BATCH * MCOLS];   // 1 MB

// ---------------------------------------------------------------------------
// Prep: convert x,T -> bf16, zero out[:, 2048:]. Uniform regions by blockIdx,
// 4 float4 per thread. blocks [0,256): x; [256,1280): T; [1280,1288): zero.
// ---------------------------------------------------------------------------
__global__ __launch_bounds__(256) void prep_kernel(
    const float* __restrict__ x, const float* __restrict__ T, float* __restrict__ out)
{
    const int bid = blockIdx.x;
    const int tid = threadIdx.x;
    if (bid < 256) {                             // x: 262144 float4
        int base = bid * 1024 + tid;
        float4 v0 = ((const float4*)x)[base];
        float4 v1 = ((const float4*)x)[base + 256];
        float4 v2 = ((const float4*)x)[base + 512];
        float4 v3 = ((const float4*)x)[base + 768];
        __nv_bfloat162* d0 = (__nv_bfloat162*)&g_xh[(base) * 4];
        __nv_bfloat162* d1 = (__nv_bfloat162*)&g_xh[(base + 256) * 4];
        __nv_bfloat162* d2 = (__nv_bfloat162*)&g_xh[(base + 512) * 4];
        __nv_bfloat162* d3 = (__nv_bfloat162*)&g_xh[(base + 768) * 4];
        d0[0] = __floats2bfloat162_rn(v0.x, v0.y); d0[1] = __floats2bfloat162_rn(v0.z, v0.w);
        d1[0] = __floats2bfloat162_rn(v1.x, v1.y); d1[1] = __floats2bfloat162_rn(v1.z, v1.w);
        d2[0] = __floats2bfloat162_rn(v2.x, v2.y); d2[1] = __floats2bfloat162_rn(v2.z, v2.w);
        d3[0] = __floats2bfloat162_rn(v3.x, v3.y); d3[1] = __floats2bfloat162_rn(v3.z, v3.w);
    } else if (bid < 1280) {                     // T: 1048576 float4... (524288)
        int base = (bid - 256) * 512 + tid;
        float4 v0 = ((const float4*)T)[base];
        float4 v1 = ((const float4*)T)[base + 256];
        __nv_bfloat162* d0 = (__nv_bfloat162*)&g_Th[(base) * 4];
        __nv_bfloat162* d1 = (__nv_bfloat162*)&g_Th[(base + 256) * 4];
        d0[0] = __floats2bfloat162_rn(v0.x, v0.y); d0[1] = __floats2bfloat162_rn(v0.z, v0.w);
        d1[0] = __floats2bfloat162_rn(v1.x, v1.y); d1[1] = __floats2bfloat162_rn(v1.z, v1.w);
    } else {                                     // zero tail: 8192 float4
        int base = (bid - 1280) * 1024 + tid;
#pragma unroll
        for (int it = 0; it < 4; ++it) {
            int i = base + it * 256;
            int row = i >> 4, c = i & 15;
            ((float4*)&out[row * OUTW + CIN])[c] = make_float4(0.f, 0.f, 0.f, 0.f);
        }
    }
}

// ---------------------------------------------------------------------------
// GEMM bf16 (R9 config, unchanged): mma.m16n8k16, 4-stage cp.async ring.
// BM=32 BN=64 BK=32, 128 threads (4 warps, 2m x 2n, warp tile 16x32).
// ---------------------------------------------------------------------------
__device__ __forceinline__ void cp16(unsigned s, const void* g) {
    asm volatile("cp.async.cg.shared.global [%0], [%1], 16;" :: "r"(s), "l"(g));
}
#define CP_COMMIT()  asm volatile("cp.async.commit_group;")
#define CP_WAIT(N)   asm volatile("cp.async.wait_group %0;" :: "n"(N))

__device__ __forceinline__ void ldm_x4(unsigned* r, unsigned addr) {
    asm volatile("ldmatrix.sync.aligned.m8n8.x4.shared.b16 {%0,%1,%2,%3}, [%4];"
        : "=r"(r[0]), "=r"(r[1]), "=r"(r[2]), "=r"(r[3]) : "r"(addr));
}
__device__ __forceinline__ void ldm_x4t(unsigned* r, unsigned addr) {
    asm volatile("ldmatrix.sync.aligned.m8n8.x4.trans.shared.b16 {%0,%1,%2,%3}, [%4];"
        : "=r"(r[0]), "=r"(r[1]), "=r"(r[2]), "=r"(r[3]) : "r"(addr));
}
__device__ __forceinline__ void mma_bf16(float* d, const unsigned* a, const unsigned* b) {
    asm volatile(
        "mma.sync.aligned.m16n8k16.row.col.f32.bf16.bf16.f32 "
        "{%0,%1,%2,%3}, {%4,%5,%6,%7}, {%8,%9}, {%0,%1,%2,%3};\n"
        : "+f"(d[0]), "+f"(d[1]), "+f"(d[2]), "+f"(d[3])
        : "r"(a[0]), "r"(a[1]), "r"(a[2]), "r"(a[3]), "r"(b[0]), "r"(b[1]));
}

#define NSTAGE 4
#define NPANEL 64

__global__ __launch_bounds__(128) void gemm_bf16(__half* __restrict__ mh)
{
    __shared__ __nv_bfloat16 As[NSTAGE][32][40];
    __shared__ __nv_bfloat16 Bs[NSTAGE][32][72];

    const int tid  = threadIdx.x;
    const int lane = tid & 31;
    const int wid  = tid >> 5;
    const int wm   = wid & 1;
    const int wn   = wid >> 1;
    const int row0 = blockIdx.y * 32;
    const int col0 = blockIdx.x * 64;

    const int aRow = tid >> 2, aC = (tid & 3) * 8;
    const int bRow = tid >> 2, bC = (tid & 3) * 16;

    const __nv_bfloat16* gA = &g_xh[(row0 + aRow) * CIN + aC];
    const __nv_bfloat16* gB = &g_Th[bRow * MCOLS + col0 + bC];

    float d[2][2][4];
#pragma unroll
    for (int i = 0; i < 2; ++i)
#pragma unroll
        for (int j = 0; j < 2; ++j)
#pragma unroll
            for (int k = 0; k < 4; ++k) d[i][j][k] = 0.0f;

#pragma unroll
    for (int s = 0; s < NSTAGE - 1; ++s) {
        cp16(__cvta_generic_to_shared(&As[s][aRow][aC]), gA + s * 32);
        cp16(__cvta_generic_to_shared(&Bs[s][bRow][bC]),     gB + s * 32 * MCOLS);
        cp16(__cvta_generic_to_shared(&Bs[s][bRow][bC + 8]), gB + s * 32 * MCOLS + 8);
        CP_COMMIT();
    }

    for (int p = 0; p < NPANEL; ++p) {
        CP_WAIT(NSTAGE - 2);
        __syncthreads();
        if (p + NSTAGE - 1 < NPANEL) {
            const int s  = (p + NSTAGE - 1) & (NSTAGE - 1);
            const int k0 = (p + NSTAGE - 1) * 32;
            cp16(__cvta_generic_to_shared(&As[s][aRow][aC]), gA + k0);
            cp16(__cvta_generic_to_shared(&Bs[s][bRow][bC]),     gB + k0 * MCOLS);
            cp16(__cvta_generic_to_shared(&Bs[s][bRow][bC + 8]), gB + k0 * MCOLS + 8);
        }
        CP_COMMIT();
        const int buf = p & (NSTAGE - 1);

#pragma unroll
        for (int kk = 0; kk < 32; kk += 16) {
            unsigned a[4];
            unsigned adrA = __cvta_generic_to_shared(
                &As[buf][wm * 16 + (lane & 15)][kk + (lane >> 4) * 8]);
            ldm_x4(a, adrA);
#pragma unroll
            for (int bi = 0; bi < 2; ++bi) {
                unsigned bb[4];
                unsigned adrB = __cvta_generic_to_shared(
                    &Bs[buf][kk + (lane & 15)][wn * 32 + bi * 16 + (lane >> 4) * 8]);
                ldm_x4t(bb, adrB);
                mma_bf16(d[bi][0], a, bb);
                mma_bf16(d[bi][1], a, bb + 2);
            }
        }
    }

    const int g = lane >> 2, c = lane & 3;
#pragma unroll
    for (int bi = 0; bi < 2; ++bi)
#pragma unroll
        for (int h = 0; h < 2; ++h) {
            int row = row0 + wm * 16 + g;
            int col = col0 + wn * 32 + bi * 16 + h * 8 + c * 2;
            *(__half2*)&mh[row * MCOLS + col] =
                __floats2half2_rn(d[bi][h][0], d[bi][h][1]);
            *(__half2*)&mh[(row + 8) * MCOLS + col] =
                __floats2half2_rn(d[bi][h][2], d[bi][h][3]);
        }
}

// ---------------------------------------------------------------------------
// Pairwise v3: grid (jh=4, bt=4, o=64) = 1024 blocks x 128 thr; 128 j/block.
// STRONG 4-group screen (sum of |dG| over 4 groups, lower-bounds L1 dist),
// packed as uint2 per j -> one LDS.128 per j-pair; ONE vote per 8 j's.
// Full path only on vote pass (diagonal). Folds x->out (2 float4/thread).
// ---------------------------------------------------------------------------
__global__ __launch_bounds__(128) void pairwise_kernel(
    const __half* __restrict__ mh, const float* __restrict__ x, float* __restrict__ out)
{
    __shared__ uint4 sjt[128][2];                  // staged j rows
    __shared__ __align__(16) uint2 sG[128];        // per-j packed group sums

    const int jh  = blockIdx.x;
    const int bt  = blockIdx.y;
    const int o   = blockIdx.z;
    const int tid = threadIdx.x;
    const int b   = bt * 128 + tid;

    // folded x -> out copy: 2 float4 per thread
    {
        int lin = (o * 4 + bt) * 4 + jh;           // 0..1023
#pragma unroll
        for (int it = 0; it < 2; ++it) {
            int id  = lin * 256 + it * 128 + tid;
            int row = id >> 9, c4 = id & 511;
            ((float4*)&out[row * OUTW])[c4] = ((const float4*)&x[row * CIN])[c4];
        }
    }

    // own row + group sums (G0..G3), packed as two half2: (G0,G1), (G2,G3)
    __half2 v[8], vg01, vg23;
    {
        const uint4* vp = (const uint4*)&mh[b * MCOLS + o * KDIM];
        *(uint4*)&v[0] = vp[0];
        *(uint4*)&v[4] = vp[1];
        __half2 t01 = __hadd2(v[0], v[1]);
        __half2 t23 = __hadd2(v[2], v[3]);
        __half2 t45 = __hadd2(v[4], v[5]);
        __half2 t67 = __hadd2(v[6], v[7]);
        vg01 = __halves2half2(__hadd(__low2half(t01), __high2half(t01)),
                              __hadd(__low2half(t23), __high2half(t23)));
        vg23 = __halves2half2(__hadd(__low2half(t45), __high2half(t45)),
                              __hadd(__low2half(t67), __high2half(t67)));
    }

    // stage j rows + packed group sums (one row per thread)
    {
        int j = jh * 128 + tid;
        const uint4* jp = (const uint4*)&mh[j * MCOLS + o * KDIM];
        uint4 w0 = jp[0], w1 = jp[1];
        sjt[tid][0] = w0;
        sjt[tid][1] = w1;
        __half2 s[8];
        *(uint4*)&s[0] = w0;
        *(uint4*)&s[4] = w1;
        __half2 a01 = __hadd2(s[0], s[1]);
        __half2 a23 = __hadd2(s[2], s[3]);
        __half2 a45 = __hadd2(s[4], s[5]);
        __half2 a67 = __hadd2(s[6], s[7]);
        __half2 g01 = __halves2half2(__hadd(__low2half(a01), __high2half(a01)),
                                     __hadd(__low2half(a23), __high2half(a23)));
        __half2 g23 = __halves2half2(__hadd(__low2half(a45), __high2half(a45)),
                                     __hadd(__low2half(a67), __high2half(a67)));
        uint2 pk;
        pk.x = *(unsigned*)&g01;
        pk.y = *(unsigned*)&g23;
        sG[tid] = pk;
    }
    __syncthreads();

    const __half2 big = __half2half2(__float2half(60000.0f));
    float acc = 0.0f;
    for (int gr = 0; gr < 16; ++gr) {              // 8 j's per vote group
        __half2 mn2 = big;
#pragma unroll
        for (int u = 0; u < 4; ++u) {              // pair (j0,j1) = gr*8+u*2
            uint4 sv = *(const uint4*)&sG[gr * 8 + u * 2];
            __half2 w01a = *(__half2*)&sv.x;       // j0: (G0,G1)
            __half2 w23a = *(__half2*)&sv.y;       // j0: (G2,G3)
            __half2 w01b = *(__half2*)&sv.z;       // j1
            __half2 w23b = *(__half2*)&sv.w;
            __half2 ea = __hadd2(__habs2(__hsub2(vg01, w01a)),
                                 __habs2(__hsub2(vg23, w23a)));
            __half2 eb = __hadd2(__habs2(__hsub2(vg01, w01b)),
                                 __habs2(__hsub2(vg23, w23b)));
            // et2 = (sum ea, sum eb)
            __half2 et2 = __halves2half2(__hadd(__low2half(ea), __high2half(ea)),
                                         __hadd(__low2half(eb), __high2half(eb)));
            mn2 = __hmin2(mn2, et2);
        }
        float mn = __half2float(__hmin(__low2half(mn2), __high2half(mn2)));
        if (__any_sync(0xffffffffu, mn < 30.0f)) {
#pragma unroll
            for (int t = 0; t < 8; ++t) {
                const int jj = gr * 8 + t;
                __half2 s[8];
                *(uint4*)&s[0] = sjt[jj][0];
                *(uint4*)&s[4] = sjt[jj][1];
                __half2 q0 = __habs2(__hsub2(v[0], s[0]));
                __half2 q1 = __habs2(__hsub2(v[1], s[1]));
                __half2 q2 = __habs2(__hsub2(v[2], s[2]));
                __half2 q3 = __habs2(__hsub2(v[3], s[3]));
                __half2 q4 = __habs2(__hsub2(v[4], s[4]));
                __half2 q5 = __habs2(__hsub2(v[5], s[5]));
                __half2 q6 = __habs2(__hsub2(v[6], s[6]));
                __half2 q7 = __habs2(__hsub2(v[7], s[7]));
                __half2 sm = __hadd2(__hadd2(__hadd2(q0, q1), __hadd2(q2, q3)),
                                     __hadd2(__hadd2(q4, q5), __hadd2(q6, q7)));
                float dist = __low2float(sm) + __high2float(sm);
                acc += __expf(-dist);
            }
        }
    }

    atomicAdd(&out[b * OUTW + CIN + o], acc);
}

extern "C" void kernel_launch(void* const* d_in, const int* in_sizes, int n_in,
                              void* d_out, int out_size)
{
    const float* x = (const float*)d_in[0];
    const float* T = (const float*)d_in[1];
    float* out = (float*)d_out;

    __half* mh;
    cudaGetSymbolAddress((void**)&mh, g_mh);

    prep_kernel<<<1288, 256>>>(x, T, out);
    gemm_bf16<<<dim3(MCOLS / 64, BATCH / 32), 128>>>(mh);
    pairwise_kernel<<<dim3(4, 4, OFEAT), 128>>>(mh, x, out);
}